// round 10
// baseline (speedup 1.0000x reference)
#include <cuda_runtime.h>
#include <cuda_bf16.h>
#include <math_constants.h>

// Problem constants
#define B   2
#define NP  8192
#define C   64
#define M   4096     // NP * 0.5
#define K   128
#define H   128
#define R2  0.04f    // 0.2^2
#define BM  (B*M)    // 8192 centers total

#define NCELL 512    // 8x8x8 Morton-ordered cells, ~16 pts/cell

// ---------------- scratch (device globals; no allocation allowed) ----------------
__device__ int   g_flags[B*NP];
__device__ int   g_sidx[BM];
__device__ float g_Y[(size_t)B*NP*H];
__device__ int   g_nbr[(size_t)BM*K];
__device__ int   g_ncnt[BM];
__device__ int   g_cellcnt[B*NCELL];
__device__ int   g_cellofs[B*NCELL];
__device__ int   g_perm[B*NP];               // Morton-sorted point order

// ---------------- packed f32x2 helpers (conv only) ----------------
__device__ __forceinline__ unsigned long long pack2f(float lo, float hi) {
    unsigned long long r;
    asm("mov.b64 %0, {%1, %2};" : "=l"(r) : "f"(lo), "f"(hi));
    return r;
}
__device__ __forceinline__ unsigned long long fma2(unsigned long long a,
                                                   unsigned long long b,
                                                   unsigned long long c) {
    unsigned long long d;
    asm("fma.rn.f32x2 %0, %1, %2, %3;" : "=l"(d) : "l"(a), "l"(b), "l"(c));
    return d;
}
__device__ __forceinline__ float2 unpack2f(unsigned long long v) {
    float lo, hi;
    asm("mov.b64 {%0, %1}, %2;" : "=f"(lo), "=f"(hi) : "l"(v));
    return make_float2(lo, hi);
}

// Morton: interleave 3x3-bit coords -> 9-bit id (consecutive ids = compact brick)
__device__ __forceinline__ int expand3(int v) {
    return (v & 1) | ((v & 2) << 2) | ((v & 4) << 4);
}
__device__ __forceinline__ int morton_cell(float x, float y, float z) {
    int cx = min(7, max(0, (int)(x * 8.0f)));
    int cy = min(7, max(0, (int)(y * 8.0f)));
    int cz = min(7, max(0, (int)(z * 8.0f)));
    return expand3(cx) | (expand3(cy) << 1) | (expand3(cz) << 2);
}

// ---------------- K0: zero flags + cell counts ----------------
__global__ void zero_kernel() {
    int i = blockIdx.x * blockDim.x + threadIdx.x;
    if (i < B*NP) g_flags[i] = 0;
    if (i < B*NCELL) g_cellcnt[i] = 0;
}

// ---------------- K0b/c/d: counting sort by Morton cell ----------------
__global__ void cellcount_kernel(const float* __restrict__ pos) {
    int i = blockIdx.x * blockDim.x + threadIdx.x;
    if (i >= B*NP) return;
    int b = i / NP;
    const float* p = pos + (size_t)i * 3;
    atomicAdd(&g_cellcnt[b*NCELL + morton_cell(p[0], p[1], p[2])], 1);
}

__global__ void cellscan_kernel() {   // grid = B, block = NCELL
    __shared__ int s[NCELL];
    const int b = blockIdx.x, t = threadIdx.x;
    s[t] = g_cellcnt[b*NCELL + t];
    __syncthreads();
    int v = s[t];
    #pragma unroll
    for (int off = 1; off < NCELL; off <<= 1) {
        int u = (t >= off) ? s[t - off] : 0;
        __syncthreads();
        v += u; s[t] = v;
        __syncthreads();
    }
    g_cellofs[b*NCELL + t] = v - g_cellcnt[b*NCELL + t];  // exclusive
}

__global__ void cellscatter_kernel(const float* __restrict__ pos) {
    int i = blockIdx.x * blockDim.x + threadIdx.x;
    if (i >= B*NP) return;
    int b = i / NP, li = i - b*NP;
    const float* p = pos + (size_t)i * 3;
    int c = morton_cell(p[0], p[1], p[2]);
    int slot = atomicAdd(&g_cellofs[b*NCELL + c], 1);
    g_perm[b*NP + slot] = li;
}

// ---------------- K1: FPS with exact warp-uniform chunk pruning ----------------
#define T_FPS 512
#define PTS   16                 // points per lane; warp chunk = 512 pts
#define NW    (T_FPS / 32)       // 16 warps

__global__ void __launch_bounds__(T_FPS, 1)
fps_kernel(const float* __restrict__ pos) {
    const int b   = blockIdx.x;
    const int tid = threadIdx.x;
    const int lane = tid & 31, wid = tid >> 5;

    extern __shared__ float4 sp[];               // coords by ORIGINAL index (128KB)
    __shared__ unsigned long long s_vi[2][NW];   // (value<<32)|origidx, parity-buffered

    const float* pb = pos + (size_t)b * NP * 3;
    for (int i = tid; i < NP; i += T_FPS)
        sp[i] = make_float4(pb[i*3+0], pb[i*3+1], pb[i*3+2], 0.0f);
    if (tid == 0) g_flags[b*NP + 0] = 1;   // idx[0] = 0
    __syncthreads();

    // thread's 16 Morton-contiguous points + packed orig indices
    float sx[PTS], sy[PTS], sz[PTS], mind[PTS];
    unsigned pid2[PTS/2];
    const int pbase = wid * 512 + lane * PTS;
    #pragma unroll
    for (int k = 0; k < PTS; k += 2) {
        int j0 = g_perm[b*NP + pbase + k];
        int j1 = g_perm[b*NP + pbase + k + 1];
        float4 a = sp[j0], q = sp[j1];
        sx[k] = a.x; sy[k] = a.y; sz[k] = a.z;
        sx[k+1] = q.x; sy[k+1] = q.y; sz[k+1] = q.z;
        pid2[k >> 1] = (unsigned)j0 | ((unsigned)j1 << 16);
        mind[k] = CUDART_INF_F; mind[k+1] = CUDART_INF_F;
    }

    // warp chunk centroid (shfl-reduced; identical bits in all lanes)
    float tx = 0.f, ty = 0.f, tz = 0.f;
    #pragma unroll
    for (int k = 0; k < PTS; k++) { tx += sx[k]; ty += sy[k]; tz += sz[k]; }
    #pragma unroll
    for (int off = 16; off; off >>= 1) {
        tx += __shfl_xor_sync(0xffffffffu, tx, off);
        ty += __shfl_xor_sync(0xffffffffu, ty, off);
        tz += __shfl_xor_sync(0xffffffffu, tz, off);
    }
    const float ccx = tx * (1.0f/512.0f), ccy = ty * (1.0f/512.0f), ccz = tz * (1.0f/512.0f);
    float r2m = 0.f;
    #pragma unroll
    for (int k = 0; k < PTS; k++) {
        float dx = sx[k]-ccx, dy = sy[k]-ccy, dz = sz[k]-ccz;
        r2m = fmaxf(r2m, fmaf(dx,dx,fmaf(dy,dy,dz*dz)));
    }
    r2m = __uint_as_float(__reduce_max_sync(0xffffffffu, __float_as_uint(r2m)));
    const float r_w = sqrtf(r2m) * 1.0001f + 1e-6f;

    // per-warp cache: (wmax bits, orig idx); INF value forces first scan
    unsigned cvu  = 0x7f800000u;   // +inf
    unsigned cloc = 0u;

    float4 w0 = sp[0];
    float fx = w0.x, fy = w0.y, fz = w0.z;

    for (int it = 1; it < M; it++) {
        const int cur = it & 1;

        // ---- exact warp-uniform skip test ----
        float dcx = ccx - fx, dcy = ccy - fy, dcz = ccz - fz;
        float dfc = fmaf(dcx,dcx,fmaf(dcy,dcy,dcz*dcz));
        float rhs = sqrtf(__uint_as_float(cvu)) * 1.0001f + r_w;
        rhs = rhs * rhs * 1.0001f + 1e-9f;
        if (!(dfc * (1.0f - 1e-4f) >= rhs)) {
            // ---- full scan (scalar FFMA; bit-identical to reference form) ----
            float bv = 0.0f;
            #pragma unroll
            for (int k = 0; k < PTS; k++) {
                float dx = sx[k]-fx, dy = sy[k]-fy, dz = sz[k]-fz;
                float d  = fmaf(dx,dx,fmaf(dy,dy,dz*dz));
                float m  = fminf(mind[k], d);
                mind[k] = m;
                bv = fmaxf(bv, m);
            }
            const unsigned bvu  = __float_as_uint(bv);
            const unsigned wmax = __reduce_max_sync(0xffffffffu, bvu);
            // first-max (min orig idx) among lanes/slots achieving wmax
            unsigned cand = 0xffffffffu;
            if (bvu == wmax) {
                const float wmf = __uint_as_float(wmax);
                #pragma unroll
                for (int k = 0; k < PTS; k++)
                    if (mind[k] == wmf)
                        cand = min(cand, (pid2[k >> 1] >> ((k & 1) * 16)) & 0xffffu);
            }
            cloc = __reduce_min_sync(0xffffffffu, cand);
            cvu  = wmax;
        }
        if (lane == 0)
            s_vi[cur][wid] = ((unsigned long long)cvu << 32) | cloc;
        __syncthreads();   // single barrier; slots parity-buffered

        // ---- block stage: every warp reduces all 16 warp results ----
        const unsigned long long pv = s_vi[cur][lane & (NW-1)];
        const unsigned hv = (unsigned)(pv >> 32);
        const unsigned g  = __reduce_max_sync(0xffffffffu, hv);
        const unsigned ic = (hv == g) ? (unsigned)pv : 0xffffffffu;
        const unsigned widx = __reduce_min_sync(0xffffffffu, ic);

        const float4 w = sp[widx];
        fx = w.x; fy = w.y; fz = w.z;
        if (tid == 0) g_flags[b*NP + widx] = 1;
    }
}

// ---------------- K2: compaction of flags -> sorted sample indices ----------------
__global__ void compact_kernel() {   // grid = B, block = 32
    const int b = blockIdx.x, lane = threadIdx.x;
    int carry = 0;
    for (int base = 0; base < NP; base += 32) {
        int f = g_flags[b*NP + base + lane];
        unsigned m = __ballot_sync(0xffffffffu, f);
        if (f) {
            int r = __popc(m & ((1u << lane) - 1u));
            g_sidx[b*M + carry + r] = base + lane;
        }
        carry += __popc(m);
    }
}

// ---------------- K3: Y = x @ W1[:C] + b1 ----------------
__global__ void ymat_kernel(const float* __restrict__ x,
                            const float* __restrict__ W1,
                            const float* __restrict__ b1) {
    const int p = blockIdx.x;
    const int h = threadIdx.x;
    __shared__ float xv[C];
    if (h < C) xv[h] = x[(size_t)p*C + h];
    __syncthreads();
    float acc = b1[h];
    #pragma unroll
    for (int c = 0; c < C; c++)
        acc = fmaf(xv[c], W1[c*H + h], acc);
    g_Y[(size_t)p*H + h] = acc;
}

// ---------------- K4: radius / top-K neighbor selection ----------------
#define CAP 2048
__global__ void radius_kernel(const float* __restrict__ pos) {  // grid = BM, block = 256
    const int ctr = blockIdx.x;
    const int b   = ctr / M;
    const int ci  = g_sidx[ctr];
    const float* pb = pos + (size_t)b * NP * 3;
    const float cx = pb[ci*3+0], cy = pb[ci*3+1], cz = pb[ci*3+2];

    __shared__ float cd[CAP];
    __shared__ int   cidx[CAP];
    __shared__ int   cnt;
    if (threadIdx.x == 0) cnt = 0;
    __syncthreads();

    for (int i = threadIdx.x; i < NP; i += 256) {
        float dx = pb[i*3+0] - cx, dy = pb[i*3+1] - cy, dz = pb[i*3+2] - cz;
        float d  = fmaf(dx, dx, fmaf(dy, dy, dz*dz));
        if (d <= R2) {
            int s = atomicAdd(&cnt, 1);
            if (s < CAP) { cd[s] = d; cidx[s] = i; }
        }
    }
    __syncthreads();
    int n = min(cnt, CAP);
    if (n <= K) {
        for (int c = threadIdx.x; c < n; c += 256)
            g_nbr[(size_t)ctr*K + c] = cidx[c];
        if (threadIdx.x == 0) g_ncnt[ctr] = n;
    } else {
        for (int c = threadIdx.x; c < n; c += 256) {
            float d = cd[c]; int id = cidx[c];
            int r = 0;
            for (int j = 0; j < n; j++) {
                float dj = cd[j];
                r += (dj < d) || (dj == d && cidx[j] < id);
            }
            if (r < K) g_nbr[(size_t)ctr*K + r] = id;
        }
        if (threadIdx.x == 0) g_ncnt[ctr] = K;
    }
}

// ---------------- K5: PointNetConv (f32x2 matmul, 4 neighbors per barrier) ----------------
#define GRP 4
__global__ void __launch_bounds__(128, 2)
conv_kernel(const float* __restrict__ pos,
            const float* __restrict__ W1,
            const float* __restrict__ W2,
            const float* __restrict__ b2,
            float* __restrict__ out) {      // grid = BM, block = 128
    const int ctr = blockIdx.x;
    const int b   = ctr / M;
    const int o   = threadIdx.x;

    unsigned long long wreg[H/2];
    #pragma unroll
    for (int k = 0; k < H; k += 2)
        wreg[k >> 1] = pack2f(W2[k*H + o], W2[(k+1)*H + o]);

    const int ci = g_sidx[ctr];
    const float* pb = pos + (size_t)b * NP * 3;
    const float cx = pb[ci*3+0], cy = pb[ci*3+1], cz = pb[ci*3+2];
    const float v0 = W1[(C+0)*H + o], v1 = W1[(C+1)*H + o], v2 = W1[(C+2)*H + o];
    const float bias2 = b2[o];

    const int n = g_ncnt[ctr];
    const int* nb = &g_nbr[(size_t)ctr*K];
    __shared__ __align__(16) float h1[2][GRP][H];

    float omax = 0.0f;

    float yv[GRP], pjx[GRP], pjy[GRP], pjz[GRP];
    #pragma unroll
    for (int g = 0; g < GRP; g++) {
        if (g < n) {
            int j = nb[g];
            yv[g]  = g_Y[(size_t)(b*NP + j)*H + o];
            pjx[g] = pb[j*3+0]; pjy[g] = pb[j*3+1]; pjz[g] = pb[j*3+2];
        }
    }

    for (int g0 = 0; g0 < n; g0 += GRP) {
        const int buf = (g0 >> 2) & 1;
        #pragma unroll
        for (int g = 0; g < GRP; g++) {
            if (g0 + g < n) {
                float hh = yv[g];
                hh = fmaf(pjx[g] - cx, v0, hh);
                hh = fmaf(pjy[g] - cy, v1, hh);
                hh = fmaf(pjz[g] - cz, v2, hh);
                h1[buf][g][o] = fmaxf(hh, 0.0f);
            }
        }
        #pragma unroll
        for (int g = 0; g < GRP; g++) {
            if (g0 + GRP + g < n) {
                int j = nb[g0 + GRP + g];
                yv[g]  = g_Y[(size_t)(b*NP + j)*H + o];
                pjx[g] = pb[j*3+0]; pjy[g] = pb[j*3+1]; pjz[g] = pb[j*3+2];
            }
        }
        __syncthreads();

        #pragma unroll
        for (int g = 0; g < GRP; g++) {
            if (g0 + g < n) {
                const ulonglong2* hp = (const ulonglong2*)&h1[buf][g][0];
                unsigned long long a0 = 0ull, a1 = 0ull, a2 = 0ull, a3 = 0ull;
                #pragma unroll
                for (int q = 0; q < H/4; q += 2) {
                    ulonglong2 hv = hp[q];
                    a0 = fma2(hv.x, wreg[2*q + 0], a0);
                    a1 = fma2(hv.y, wreg[2*q + 1], a1);
                    ulonglong2 hw = hp[q + 1];
                    a2 = fma2(hw.x, wreg[2*q + 2], a2);
                    a3 = fma2(hw.y, wreg[2*q + 3], a3);
                }
                float2 f0 = unpack2f(a0), f1 = unpack2f(a1);
                float2 f2 = unpack2f(a2), f3 = unpack2f(a3);
                float s = ((f0.x + f0.y) + (f1.x + f1.y)) + ((f2.x + f2.y) + (f3.x + f3.y));
                omax = fmaxf(omax, fmaxf(s + bias2, 0.0f));
            }
        }
    }
    out[(size_t)ctr*H + o] = (n > 0) ? omax : 0.0f;
}

// ---------------- K6: pack auxiliary outputs (qpos, batch) if expected ----------------
__global__ void pack_kernel(const float* __restrict__ pos, float* __restrict__ out,
                            int out_size) {
    const int i = blockIdx.x * blockDim.x + threadIdx.x;
    if (i >= BM) return;
    const int b  = i / M;
    const int ci = g_sidx[i];
    const float* pb = pos + (size_t)b * NP * 3;
    const int base_q = BM * H;
    if (out_size >= base_q + BM*3) {
        out[base_q + i*3 + 0] = pb[ci*3+0];
        out[base_q + i*3 + 1] = pb[ci*3+1];
        out[base_q + i*3 + 2] = pb[ci*3+2];
    }
    const int base_b = base_q + BM*3;
    if (out_size >= base_b + BM) {
        out[base_b + i] = (float)b;
    }
}

// ---------------- launch ----------------
extern "C" void kernel_launch(void* const* d_in, const int* in_sizes, int n_in,
                              void* d_out, int out_size) {
    const float* x    = (const float*)d_in[0];
    const float* pos  = (const float*)d_in[1];
    const float* W1   = (const float*)d_in[3];
    const float* b1   = (const float*)d_in[4];
    const float* W2   = (const float*)d_in[5];
    const float* b2   = (const float*)d_in[6];
    float* out = (float*)d_out;

    const int fps_smem = NP * (int)sizeof(float4);   // 128KB float4 pos cache
    cudaFuncSetAttribute(fps_kernel, cudaFuncAttributeMaxDynamicSharedMemorySize, fps_smem);

    zero_kernel<<<(B*NP + 255)/256, 256>>>();
    cellcount_kernel<<<(B*NP + 255)/256, 256>>>(pos);
    cellscan_kernel<<<B, NCELL>>>();
    cellscatter_kernel<<<(B*NP + 255)/256, 256>>>(pos);
    fps_kernel<<<B, T_FPS, fps_smem>>>(pos);
    compact_kernel<<<B, 32>>>();
    ymat_kernel<<<B*NP, H>>>(x, W1, b1);
    radius_kernel<<<BM, 256>>>(pos);
    conv_kernel<<<BM, H>>>(pos, W1, W2, b2, out);
    pack_kernel<<<(BM + 255)/256, 256>>>(pos, out, out_size);
}